// round 1
// baseline (speedup 1.0000x reference)
#include <cuda_runtime.h>

#define HH 512
#define WW 512
#define BATCH 2
#define CMID 64
#define HWSZ (HH*WW)

// Persistent scratch (device globals: allocation-free, graph-capturable)
__device__ float g_bufA[BATCH*CMID*HWSZ];
__device__ float g_bufB[BATCH*CMID*HWSZ];
__device__ float g_bufC[BATCH*CMID*HWSZ];
__device__ float g_filt[BATCH*30*HWSZ];
__device__ float g_fh[BATCH*3*HWSZ];

// ---------------------------------------------------------------------------
// conv 7x7, Cin=6 -> 64, pad 3, ReLU.
// Block: 256 thr = 8 cout-groups x 32 pixel-slots; tile 8H x 16W; 4 px/thread.
// ---------------------------------------------------------------------------
__global__ __launch_bounds__(256) void conv7x7_kernel(
    const float* __restrict__ in, const float* __restrict__ wt,
    float* __restrict__ out)
{
    __shared__ float s_in[6][14][24];   // rows h0-3..h0+10, cols w0-3..w0+18 (22 used)
    __shared__ float s_w[64][7][8];     // [cout][ky][kx pad->8]

    const int tid  = threadIdx.x;
    const int cg   = tid >> 5;
    const int slot = tid & 31;
    const int pr   = slot >> 2;
    const int pc4  = (slot & 3) * 4;
    const int h0   = blockIdx.y * 8;
    const int w0   = blockIdx.x * 16;
    const int b    = blockIdx.z;

    for (int i = tid; i < 6*14*22; i += 256) {
        int ci = i / (14*22);
        int r  = (i / 22) % 14;
        int c  = i % 22;
        int gh = h0 - 3 + r;
        int gw = w0 - 3 + c;
        float v = 0.f;
        if (gh >= 0 && gh < HH && gw >= 0 && gw < WW)
            v = in[((b*6 + ci)*HH + gh)*WW + gw];
        s_in[ci][r][c] = v;
    }
    if (tid < 448) s_w[tid/7][tid%7][7] = 0.f;

    float acc[8][4];
    #pragma unroll
    for (int c = 0; c < 8; c++)
        #pragma unroll
        for (int p = 0; p < 4; p++) acc[c][p] = 0.f;

    for (int cin = 0; cin < 6; cin++) {
        __syncthreads();
        for (int i = tid; i < 64*49; i += 256) {
            int co = i / 49, k = i % 49;
            s_w[co][k/7][k%7] = wt[(co*6 + cin)*49 + k];
        }
        __syncthreads();
        #pragma unroll 1
        for (int ky = 0; ky < 7; ky++) {
            float xr[10];
            const float* rp = &s_in[cin][pr + ky][pc4];
            float4 v0 = *(const float4*)rp;
            float4 v1 = *(const float4*)(rp + 4);
            float2 v2 = *(const float2*)(rp + 8);
            xr[0]=v0.x; xr[1]=v0.y; xr[2]=v0.z; xr[3]=v0.w;
            xr[4]=v1.x; xr[5]=v1.y; xr[6]=v1.z; xr[7]=v1.w;
            xr[8]=v2.x; xr[9]=v2.y;
            #pragma unroll
            for (int c = 0; c < 8; c++) {
                const float* wp = &s_w[cg*8 + c][ky][0];
                float4 wa = *(const float4*)wp;
                float4 wb = *(const float4*)(wp + 4);
                float wv[7] = {wa.x, wa.y, wa.z, wa.w, wb.x, wb.y, wb.z};
                #pragma unroll
                for (int p = 0; p < 4; p++) {
                    float s = acc[c][p];
                    #pragma unroll
                    for (int q = 0; q < 7; q++) s += xr[p+q] * wv[q];
                    acc[c][p] = s;
                }
            }
        }
    }

    const int h = h0 + pr;
    #pragma unroll
    for (int c = 0; c < 8; c++) {
        int co = cg*8 + c;
        float4 v;
        v.x = fmaxf(acc[c][0], 0.f);
        v.y = fmaxf(acc[c][1], 0.f);
        v.z = fmaxf(acc[c][2], 0.f);
        v.w = fmaxf(acc[c][3], 0.f);
        *(float4*)&out[((b*64 + co)*HH + h)*WW + w0 + pc4] = v;
    }
}

// ---------------------------------------------------------------------------
// conv 3x3, Cin=64 -> COUT, pad 1, optional BN / ReLU / skip-add (post-ReLU).
// Block: 256 thr = 8 cout-groups x 32 pixel-slots; tile 8H x 16W; NC couts and
// 4 px per thread. Cin chunked by 8 through smem.
// ---------------------------------------------------------------------------
template<int NC, int COUT, bool BN, bool RELU, bool SKIP>
__global__ __launch_bounds__(256) void conv3x3_kernel(
    const float* __restrict__ in, const float* __restrict__ wt,
    const float* __restrict__ bng, const float* __restrict__ bnb,
    const float* __restrict__ bnm, const float* __restrict__ bnv,
    const float* __restrict__ skip, float* __restrict__ out)
{
    constexpr int CP = 8 * NC;          // couts covered per block (>= COUT)
    __shared__ float s_in[8][10][20];   // 8 cin x (8+2) rows x (16+2) cols (pad 20)
    __shared__ float s_w[8][CP][12];    // [cin][cout][9 pad->12]

    const int tid  = threadIdx.x;
    const int cg   = tid >> 5;
    const int slot = tid & 31;
    const int pr   = slot >> 2;
    const int pc4  = (slot & 3) * 4;
    const int h0   = blockIdx.y * 8;
    const int w0   = blockIdx.x * 16;
    const int b    = blockIdx.z;

    float acc[NC][4];
    #pragma unroll
    for (int c = 0; c < NC; c++)
        #pragma unroll
        for (int p = 0; p < 4; p++) acc[c][p] = 0.f;

    for (int cc = 0; cc < 8; cc++) {
        const int cin0 = cc * 8;
        __syncthreads();
        for (int i = tid; i < 8*10*18; i += 256) {
            int ci = i / 180;
            int r  = (i / 18) % 10;
            int c  = i % 18;
            int gh = h0 - 1 + r;
            int gw = w0 - 1 + c;
            float v = 0.f;
            if (gh >= 0 && gh < HH && gw >= 0 && gw < WW)
                v = in[((b*64 + cin0 + ci)*HH + gh)*WW + gw];
            s_in[ci][r][c] = v;
        }
        for (int i = tid; i < CP*72; i += 256) {
            int co = i / 72;
            int r  = i % 72;          // (ci, k) contiguous in global weights
            float v = 0.f;
            if (CP == COUT || co < COUT)
                v = wt[(co*64 + cin0)*9 + r];
            s_w[r/9][co][r%9] = v;
        }
        __syncthreads();

        #pragma unroll 2
        for (int ci = 0; ci < 8; ci++) {
            float xr[3][6];
            #pragma unroll
            for (int dr = 0; dr < 3; dr++) {
                const float* rp = &s_in[ci][pr + dr][pc4];
                float4 a  = *(const float4*)rp;
                float2 b2 = *(const float2*)(rp + 4);
                xr[dr][0]=a.x; xr[dr][1]=a.y; xr[dr][2]=a.z; xr[dr][3]=a.w;
                xr[dr][4]=b2.x; xr[dr][5]=b2.y;
            }
            #pragma unroll
            for (int c = 0; c < NC; c++) {
                const float* wp = &s_w[ci][cg*NC + c][0];
                float4 wa = *(const float4*)wp;
                float4 wb = *(const float4*)(wp + 4);
                float  wc = wp[8];
                float wv[9] = {wa.x, wa.y, wa.z, wa.w, wb.x, wb.y, wb.z, wb.w, wc};
                #pragma unroll
                for (int p = 0; p < 4; p++) {
                    float s = acc[c][p];
                    s += xr[0][p]*wv[0] + xr[0][p+1]*wv[1] + xr[0][p+2]*wv[2];
                    s += xr[1][p]*wv[3] + xr[1][p+1]*wv[4] + xr[1][p+2]*wv[5];
                    s += xr[2][p]*wv[6] + xr[2][p+1]*wv[7] + xr[2][p+2]*wv[8];
                    acc[c][p] = s;
                }
            }
        }
    }

    const int h = h0 + pr;
    #pragma unroll
    for (int c = 0; c < NC; c++) {
        const int co = cg*NC + c;
        if (CP != COUT && co >= COUT) continue;
        float vals[4];
        #pragma unroll
        for (int p = 0; p < 4; p++) vals[p] = acc[c][p];
        if (BN) {
            float sc = bng[co] * rsqrtf(bnv[co] + 1e-5f);
            float sh = bnb[co] - bnm[co] * sc;
            #pragma unroll
            for (int p = 0; p < 4; p++) vals[p] = vals[p]*sc + sh;
        }
        if (RELU) {
            #pragma unroll
            for (int p = 0; p < 4; p++) vals[p] = fmaxf(vals[p], 0.f);
        }
        const int oidx = ((b*COUT + co)*HH + h)*WW + w0 + pc4;
        if (SKIP) {
            float4 sk = *(const float4*)&skip[oidx];
            vals[0] += sk.x; vals[1] += sk.y; vals[2] += sk.z; vals[3] += sk.w;
        }
        float4 v = {vals[0], vals[1], vals[2], vals[3]};
        *(float4*)&out[oidx] = v;
    }
}

// ---------------------------------------------------------------------------
// Adaptive filtering. Channel c of the 30-ch conv output maps to
// (color = c/10, tap j = c%10): j<5 -> vertical weights, j>=5 -> horizontal.
// ---------------------------------------------------------------------------
__global__ __launch_bounds__(256) void filt_h_kernel(
    const float* __restrict__ filt, const float* __restrict__ base,
    float* __restrict__ fh)
{
    int idx = blockIdx.x * 256 + threadIdx.x;   // [b][ch][h][w]
    int w  = idx & 511;
    int h  = (idx >> 9) & 511;
    int bc = idx >> 18;          // b*3 + ch
    int ch = bc % 3;
    int b  = bc / 3;

    const float* lp = filt + ((b*30 + ch*10)*HH + h)*WW + w;
    float l[5];
    #pragma unroll
    for (int i = 0; i < 5; i++) l[i] = lp[i*HWSZ];
    float m = fmaxf(fmaxf(fmaxf(l[0], l[1]), fmaxf(l[2], l[3])), l[4]);
    float e[5], s = 0.f;
    #pragma unroll
    for (int i = 0; i < 5; i++) { e[i] = __expf(l[i] - m); s += e[i]; }
    float inv = 1.f / s;

    const float* bp = base + bc*HWSZ + w;
    float r = 0.f;
    #pragma unroll
    for (int i = 0; i < 5; i++) {
        int hh2 = h - 2 + i;
        float bv = (hh2 >= 0 && hh2 < HH) ? bp[hh2*WW] : 0.f;
        r += bv * e[i] * inv;
    }
    fh[idx] = r;
}

__global__ __launch_bounds__(256) void filt_w_kernel(
    const float* __restrict__ filt, const float* __restrict__ fh,
    float* __restrict__ out)
{
    int idx = blockIdx.x * 256 + threadIdx.x;
    int w  = idx & 511;
    int h  = (idx >> 9) & 511;
    int bc = idx >> 18;
    int ch = bc % 3;
    int b  = bc / 3;

    const float* lp = filt + ((b*30 + ch*10 + 5)*HH + h)*WW + w;
    float l[5];
    #pragma unroll
    for (int i = 0; i < 5; i++) l[i] = lp[i*HWSZ];
    float m = fmaxf(fmaxf(fmaxf(l[0], l[1]), fmaxf(l[2], l[3])), l[4]);
    float e[5], s = 0.f;
    #pragma unroll
    for (int i = 0; i < 5; i++) { e[i] = __expf(l[i] - m); s += e[i]; }
    float inv = 1.f / s;

    const float* fp = fh + (bc*HH + h)*WW;
    float r = 0.f;
    #pragma unroll
    for (int i = 0; i < 5; i++) {
        int ww2 = w - 2 + i;
        float fv = (ww2 >= 0 && ww2 < WW) ? fp[ww2] : 0.f;
        r += fv * e[i] * inv;
    }
    out[idx] = r;
}

// ---------------------------------------------------------------------------
extern "C" void kernel_launch(void* const* d_in, const int* in_sizes, int n_in,
                              void* d_out, int out_size)
{
    const float* fm     = (const float*)d_in[0];
    const float* base   = (const float*)d_in[1];
    const float* wfirst = (const float*)d_in[2];
    const float* kbw1   = (const float*)d_in[3];
    const float* kbg1   = (const float*)d_in[4];
    const float* kbb1   = (const float*)d_in[5];
    const float* kbm1   = (const float*)d_in[6];
    const float* kbv1   = (const float*)d_in[7];
    const float* kbw2   = (const float*)d_in[8];
    const float* kbg2   = (const float*)d_in[9];
    const float* kbb2   = (const float*)d_in[10];
    const float* kbm2   = (const float*)d_in[11];
    const float* kbv2   = (const float*)d_in[12];
    const float* wlast  = (const float*)d_in[13];
    float* out = (float*)d_out;

    float *A, *Bf, *Cbuf, *F, *FHp;
    cudaGetSymbolAddress((void**)&A,    g_bufA);
    cudaGetSymbolAddress((void**)&Bf,   g_bufB);
    cudaGetSymbolAddress((void**)&Cbuf, g_bufC);
    cudaGetSymbolAddress((void**)&F,    g_filt);
    cudaGetSymbolAddress((void**)&FHp,  g_fh);

    dim3 grid(WW/16, HH/8, BATCH), blk(256);

    conv7x7_kernel<<<grid, blk>>>(fm, wfirst, A);

    float* cur   = A;
    float* spare = Cbuf;
    for (int i = 0; i < 4; i++) {
        conv3x3_kernel<8,64,true,true,false><<<grid, blk>>>(
            cur, kbw1 + i*36864,
            kbg1 + i*64, kbb1 + i*64, kbm1 + i*64, kbv1 + i*64,
            nullptr, Bf);
        conv3x3_kernel<8,64,true,true,true><<<grid, blk>>>(
            Bf, kbw2 + i*36864,
            kbg2 + i*64, kbb2 + i*64, kbm2 + i*64, kbv2 + i*64,
            cur, spare);
        float* t = cur; cur = spare; spare = t;
    }

    conv3x3_kernel<4,30,false,false,false><<<grid, blk>>>(
        cur, wlast, nullptr, nullptr, nullptr, nullptr, nullptr, F);

    int npix = BATCH*3*HWSZ;
    filt_h_kernel<<<npix/256, 256>>>(F, base, FHp);
    filt_w_kernel<<<npix/256, 256>>>(F, FHp, out);
}